// round 12
// baseline (speedup 1.0000x reference)
#include <cuda_runtime.h>

#define TT 100   // sequence length
#define CC 16    // input embedding dim
#define HH 64    // head size
#define DD 256   // dense dim
#define RS 20    // padded row stride: float4-aligned

typedef unsigned long long ull;

// ---- packed fp32x2 helpers (sm_100+; .rn = bit-identical rounding to FFMA) ----
__device__ __forceinline__ ull ffma2(ull a, ull b, ull acc) {
    ull d;
    asm("fma.rn.f32x2 %0, %1, %2, %3;" : "=l"(d) : "l"(a), "l"(b), "l"(acc));
    return d;
}
__device__ __forceinline__ ull add2(ull a, ull b) {
    ull d;
    asm("add.rn.f32x2 %0, %1, %2;" : "=l"(d) : "l"(a), "l"(b));
    return d;
}
__device__ __forceinline__ ull mul2(ull a, ull b) {
    ull d;
    asm("mul.rn.f32x2 %0, %1, %2;" : "=l"(d) : "l"(a), "l"(b));
    return d;
}
__device__ __forceinline__ ull pack2(float lo, float hi) {
    ull r;
    asm("mov.b64 %0, {%1, %2};" : "=l"(r) : "f"(lo), "f"(hi));
    return r;
}
__device__ __forceinline__ float hadd2(ull v) {
    float lo, hi;
    asm("mov.b64 {%0, %1}, %2;" : "=f"(lo), "=f"(hi) : "l"(v));
    return lo + hi;
}

// ---- MUFU-free expf. Magic-number rint + deg-5 poly for 2^f. ----
__device__ __forceinline__ float fast_exp(float x) {
    const float L2E   = 1.4426950408889634f;
    const float MAGIC = 12582912.0f;          // 1.5 * 2^23
    x = fmaxf(x, -80.0f);
    float y = fmaf(x, L2E, MAGIC);
    float f = fmaf(x, L2E, MAGIC - y);
    float p = 1.3333558146428443e-3f;
    p = fmaf(p, f, 9.6181291076284771e-3f);
    p = fmaf(p, f, 5.5504108664821579e-2f);
    p = fmaf(p, f, 2.4022650695910071e-1f);
    p = fmaf(p, f, 6.9314718055994531e-1f);
    p = fmaf(p, f, 1.0f);
    return __int_as_float(__float_as_int(p) + (__float_as_int(y) << 23));
}

#define BAR_G() asm volatile("bar.sync %0, %1;" :: "r"(g + 1), "r"(128) : "memory")

// Folded weights (computed by the prologue each call — deterministic)
__device__ float g_Wvc[CC * DD];
__device__ float g_M[CC * CC];

// ---------------------------------------------------------------------------
// Prologue (512 threads, 2 blocks):
//   block 0: g_Wvc fold, h-range split across thread halves + smem reduce
//   block 1: g_M — q-fold / k-fold in parallel halves, then split-d dot
// ---------------------------------------------------------------------------
__global__ void __launch_bounds__(512)
prologue_kernel(const float* __restrict__ Wk, const float* __restrict__ Wq,
                const float* __restrict__ Wv, const float* __restrict__ Wdk,
                const float* __restrict__ Wdq, const float* __restrict__ Wdv) {
    __shared__ float buf[10752];

    int tid  = threadIdx.x;
    int d    = tid & 255;
    int half = tid >> 8;

    if (blockIdx.x == 0) {
        float* w1s  = buf;
        float* part = buf + 1024;
        for (int i = tid; i < CC * HH; i += 512) w1s[i] = Wv[i];
        __syncthreads();

        float w2r[32];
#pragma unroll
        for (int hh = 0; hh < 32; hh++) w2r[hh] = Wdv[(half * 32 + hh) * DD + d];

        float acc[CC];
#pragma unroll
        for (int c = 0; c < CC; c++) {
            float a0 = 0.f, a1 = 0.f;
#pragma unroll
            for (int hh = 0; hh < 32; hh += 2) {
                a0 += w1s[c * HH + half * 32 + hh]     * w2r[hh];
                a1 += w1s[c * HH + half * 32 + hh + 1] * w2r[hh + 1];
            }
            acc[c] = a0 + a1;
        }
        if (half == 1)
#pragma unroll
            for (int c = 0; c < CC; c++) part[c * DD + d] = acc[c];
        __syncthreads();
        if (half == 0)
#pragma unroll
            for (int c = 0; c < CC; c++) g_Wvc[c * DD + d] = acc[c] + part[c * DD + d];
    } else {
        float* w1a  = buf;
        float* w1b  = buf + 1024;
        float* qcs  = buf + 2048;
        float* kcs  = buf + 2048 + 4096;
        float* dotp = buf + 2048 + 8192;

        for (int i = tid; i < CC * HH; i += 512) { w1a[i] = Wq[i]; w1b[i] = Wk[i]; }
        __syncthreads();

        const float* W2 = half ? Wdk : Wdq;
        const float* w1 = half ? w1b : w1a;
        float* ocs = half ? kcs : qcs;
        float w2r[HH];
#pragma unroll
        for (int h = 0; h < HH; h++) w2r[h] = W2[h * DD + d];
#pragma unroll
        for (int c = 0; c < CC; c++) {
            float a0 = 0.f, a1 = 0.f;
#pragma unroll
            for (int h = 0; h < HH; h += 2) {
                a0 += w1[c * HH + h]     * w2r[h];
                a1 += w1[c * HH + h + 1] * w2r[h + 1];
            }
            ocs[d * CC + c] = a0 + a1;
        }
        __syncthreads();

        int c  = (tid & 255) >> 4;
        int c2 = tid & 15;
        int d0 = half * 128;
        float s0 = 0.f, s1 = 0.f;
#pragma unroll 8
        for (int dd = d0; dd < d0 + 128; dd += 2) {
            s0 += qcs[dd * CC + c] * kcs[dd * CC + c2];
            s1 += qcs[(dd + 1) * CC + c] * kcs[(dd + 1) * CC + c2];
        }
        dotp[tid] = s0 + s1;
        __syncthreads();
        if (half == 0)
            g_M[c * CC + c2] = (dotp[tid] + dotp[tid + 256]) * 0.25f;
    }
}

// ---------------------------------------------------------------------------
// Main kernel: two independent 128-thread groups per CTA (named barriers).
// y is computed IN-LANE inside the fused phase (bit-identical FFMA order) —
// the separate y phase, its barrier, and the yz round-trip are gone. Only two
// syncs remain: after the cooperative x load, and before the out projection.
// Fused phase: warp owns a contiguous 25-row block (trip counts 26/50/76/100);
// group 1's block order reversed for SMSP balance.
// ---------------------------------------------------------------------------
__global__ void __launch_bounds__(256, 3)
head_kernel(const float* __restrict__ x, float* __restrict__ out, int B) {
    extern __shared__ float sm[];
    const int tid  = threadIdx.x;
    const int g    = tid >> 7;       // group 0/1
    const int gtid = tid & 127;
    const int wg   = (tid >> 5) & 3; // warp in group
    const int lane = tid & 31;

    float* xs = sm + g * (2 * TT * RS);   // 2000
    float* yz = xs + TT * RS;             // 2000 (z only now)
    float* Ms = sm + 4 * TT * RS;         // 256

    const long long b = 2LL * blockIdx.x + g;
    const float* xb = x + b * (long long)(TT * CC);

    // x tile via float4 loads + M
    for (int i = gtid; i < (TT * CC) / 4; i += 128) {
        float4 v = reinterpret_cast<const float4*>(xb)[i];
        int t = i >> 2, c4 = (i & 3) * 4;
        *reinterpret_cast<float4*>(&xs[t * RS + c4]) = v;
    }
    Ms[tid] = g_M[tid];   // CC*CC == 256 == blockDim
    __syncthreads();

    // ---- fused y + logits + softmax + z: one barrier-free stretch ----
    {
        const int blk = g ? (3 - wg) : wg;     // SMSP anti-correlation
        const bool rowAct = (lane < 25);
        const int t  = 25 * blk + lane;        // 25blk .. 25blk+24 when active
        const int tl = rowAct ? t : 25 * blk;
        const int sEnd = (25 * blk + 26) & ~1; // 26 / 50 / 76 / 100

        // own x row as scalars
        float xf[16];
#pragma unroll
        for (int q = 0; q < 4; q++) {
            float4 v = *reinterpret_cast<const float4*>(&xs[tl * RS + 4 * q]);
            xf[4 * q] = v.x; xf[4 * q + 1] = v.y;
            xf[4 * q + 2] = v.z; xf[4 * q + 3] = v.w;
        }

        // y row in registers: yr[j] = (y[2j], y[2j+1]); same FFMA order as the
        // old y phase -> bit-identical results.
        ull yr[8];
#pragma unroll
        for (int j = 0; j < 8; j++) yr[j] = 0ull;
#pragma unroll
        for (int c = 0; c < CC; c++) {
            ull xp = pack2(xf[c], xf[c]);
            ulonglong2 m0 = *reinterpret_cast<const ulonglong2*>(&Ms[c * CC + 0]);
            ulonglong2 m1 = *reinterpret_cast<const ulonglong2*>(&Ms[c * CC + 4]);
            ulonglong2 m2 = *reinterpret_cast<const ulonglong2*>(&Ms[c * CC + 8]);
            ulonglong2 m3 = *reinterpret_cast<const ulonglong2*>(&Ms[c * CC + 12]);
            yr[0] = ffma2(xp, m0.x, yr[0]);  yr[1] = ffma2(xp, m0.y, yr[1]);
            yr[2] = ffma2(xp, m1.x, yr[2]);  yr[3] = ffma2(xp, m1.y, yr[3]);
            yr[4] = ffma2(xp, m2.x, yr[4]);  yr[5] = ffma2(xp, m2.y, yr[5]);
            yr[6] = ffma2(xp, m3.x, yr[6]);  yr[7] = ffma2(xp, m3.y, yr[7]);
        }

        ull z[8];
#pragma unroll
        for (int j = 0; j < 8; j++) z[j] = 0ull;
        float sum = 0.f;

        const float* xp2 = xs;
        for (int s = 0; s < sEnd; s += 2, xp2 += 2 * RS) {
            ulonglong2 xa0 = *reinterpret_cast<const ulonglong2*>(xp2 + 0);
            ulonglong2 xb0 = *reinterpret_cast<const ulonglong2*>(xp2 + 4);
            ulonglong2 xc0 = *reinterpret_cast<const ulonglong2*>(xp2 + 8);
            ulonglong2 xd0 = *reinterpret_cast<const ulonglong2*>(xp2 + 12);
            ulonglong2 xa1 = *reinterpret_cast<const ulonglong2*>(xp2 + RS + 0);
            ulonglong2 xb1 = *reinterpret_cast<const ulonglong2*>(xp2 + RS + 4);
            ulonglong2 xc1 = *reinterpret_cast<const ulonglong2*>(xp2 + RS + 8);
            ulonglong2 xd1 = *reinterpret_cast<const ulonglong2*>(xp2 + RS + 12);

            ull A0 = 0ull, B0 = 0ull, A1 = 0ull, B1 = 0ull;
            A0 = ffma2(yr[0], xa0.x, A0);  B0 = ffma2(yr[1], xa0.y, B0);
            A1 = ffma2(yr[0], xa1.x, A1);  B1 = ffma2(yr[1], xa1.y, B1);
            A0 = ffma2(yr[2], xb0.x, A0);  B0 = ffma2(yr[3], xb0.y, B0);
            A1 = ffma2(yr[2], xb1.x, A1);  B1 = ffma2(yr[3], xb1.y, B1);
            A0 = ffma2(yr[4], xc0.x, A0);  B0 = ffma2(yr[5], xc0.y, B0);
            A1 = ffma2(yr[4], xc1.x, A1);  B1 = ffma2(yr[5], xc1.y, B1);
            A0 = ffma2(yr[6], xd0.x, A0);  B0 = ffma2(yr[7], xd0.y, B0);
            A1 = ffma2(yr[6], xd1.x, A1);  B1 = ffma2(yr[7], xd1.y, B1);

            float e0 = fast_exp(hadd2(add2(A0, B0)));
            float e1 = fast_exp(hadd2(add2(A1, B1)));
            e0 = (rowAct && s     <= t) ? e0 : 0.f;
            e1 = (rowAct && s + 1 <= t) ? e1 : 0.f;
            sum += e0 + e1;
            ull ep0 = pack2(e0, e0);
            ull ep1 = pack2(e1, e1);
            z[0] = ffma2(ep0, xa0.x, z[0]);  z[0] = ffma2(ep1, xa1.x, z[0]);
            z[1] = ffma2(ep0, xa0.y, z[1]);  z[1] = ffma2(ep1, xa1.y, z[1]);
            z[2] = ffma2(ep0, xb0.x, z[2]);  z[2] = ffma2(ep1, xb1.x, z[2]);
            z[3] = ffma2(ep0, xb0.y, z[3]);  z[3] = ffma2(ep1, xb1.y, z[3]);
            z[4] = ffma2(ep0, xc0.x, z[4]);  z[4] = ffma2(ep1, xc1.x, z[4]);
            z[5] = ffma2(ep0, xc0.y, z[5]);  z[5] = ffma2(ep1, xc1.y, z[5]);
            z[6] = ffma2(ep0, xd0.x, z[6]);  z[6] = ffma2(ep1, xd1.x, z[6]);
            z[7] = ffma2(ep0, xd0.y, z[7]);  z[7] = ffma2(ep1, xd1.y, z[7]);
        }

        // local normalize + write (each lane owns its full row)
        if (rowAct) {
            float inv = 1.f / sum;
            ull ip = pack2(inv, inv);
#pragma unroll
            for (int j = 0; j < 8; j++)
                *reinterpret_cast<ull*>(&yz[t * RS + 2 * j]) = mul2(z[j], ip);
        }
    }
    BAR_G();

    // ---- out = z @ Wvc ---- (thread: 2 cols x 100 rows, t-unroll 2)
    {
        int d2 = gtid;   // column pair 0..127
        ull wp[8][2];
#pragma unroll
        for (int c2 = 0; c2 < 8; c2++) {
            float2 w0 = *reinterpret_cast<const float2*>(&g_Wvc[(2 * c2 + 0) * DD + 2 * d2]);
            float2 w1 = *reinterpret_cast<const float2*>(&g_Wvc[(2 * c2 + 1) * DD + 2 * d2]);
            wp[c2][0] = pack2(w0.x, w1.x);
            wp[c2][1] = pack2(w0.y, w1.y);
        }

        float* ob = out + b * (long long)(TT * DD) + 2 * d2;
        for (int t = 0; t < TT; t += 2) {
            ull acc0 = 0ull, acc1 = 0ull, acc2 = 0ull, acc3 = 0ull;
#pragma unroll
            for (int q = 0; q < 4; q++) {
                ulonglong2 zp0 = *reinterpret_cast<const ulonglong2*>(&yz[t * RS + q * 4]);
                ulonglong2 zp1 = *reinterpret_cast<const ulonglong2*>(&yz[(t + 1) * RS + q * 4]);
                acc0 = ffma2(zp0.x, wp[2 * q + 0][0], acc0);
                acc0 = ffma2(zp0.y, wp[2 * q + 1][0], acc0);
                acc1 = ffma2(zp0.x, wp[2 * q + 0][1], acc1);
                acc1 = ffma2(zp0.y, wp[2 * q + 1][1], acc1);
                acc2 = ffma2(zp1.x, wp[2 * q + 0][0], acc2);
                acc2 = ffma2(zp1.y, wp[2 * q + 1][0], acc2);
                acc3 = ffma2(zp1.x, wp[2 * q + 0][1], acc3);
                acc3 = ffma2(zp1.y, wp[2 * q + 1][1], acc3);
            }
            float2 o0, o1;
            o0.x = hadd2(acc0);
            o0.y = hadd2(acc1);
            o1.x = hadd2(acc2);
            o1.y = hadd2(acc3);
            *reinterpret_cast<float2*>(&ob[t * DD]) = o0;
            *reinterpret_cast<float2*>(&ob[(t + 1) * DD]) = o1;
        }
    }
}

// ---------------------------------------------------------------------------
extern "C" void kernel_launch(void* const* d_in, const int* in_sizes, int n_in,
                              void* d_out, int out_size) {
    const float* x   = (const float*)d_in[0];
    const float* Wk  = (const float*)d_in[1];
    const float* Wq  = (const float*)d_in[2];
    const float* Wv  = (const float*)d_in[3];
    const float* Wdk = (const float*)d_in[4];
    const float* Wdq = (const float*)d_in[5];
    const float* Wdv = (const float*)d_in[6];
    float* out = (float*)d_out;

    int B = in_sizes[0] / (TT * CC);  // 4096

    const int smem_bytes = (4 * TT * RS + CC * CC) * (int)sizeof(float); // 33024
    cudaFuncSetAttribute(head_kernel, cudaFuncAttributeMaxDynamicSharedMemorySize, smem_bytes);

    prologue_kernel<<<2, 512>>>(Wk, Wq, Wv, Wdk, Wdq, Wdv);
    head_kernel<<<B / 2, 256, smem_bytes>>>(x, out, B);
}

// round 13
// speedup vs baseline: 1.0083x; 1.0083x over previous
#include <cuda_runtime.h>

#define TT 100   // sequence length
#define CC 16    // input embedding dim
#define HH 64    // head size
#define DD 256   // dense dim
#define RS 20    // padded row stride (also conflict-free for mma A-fragments)
#define WVS 264  // Wvc smem row stride (conflict-free B-fragments)

typedef unsigned long long ull;

// ---- packed fp32x2 helpers (sm_100+; .rn = bit-identical rounding to FFMA) ----
__device__ __forceinline__ ull ffma2(ull a, ull b, ull acc) {
    ull d;
    asm("fma.rn.f32x2 %0, %1, %2, %3;" : "=l"(d) : "l"(a), "l"(b), "l"(acc));
    return d;
}
__device__ __forceinline__ ull add2(ull a, ull b) {
    ull d;
    asm("add.rn.f32x2 %0, %1, %2;" : "=l"(d) : "l"(a), "l"(b));
    return d;
}
__device__ __forceinline__ ull mul2(ull a, ull b) {
    ull d;
    asm("mul.rn.f32x2 %0, %1, %2;" : "=l"(d) : "l"(a), "l"(b));
    return d;
}
__device__ __forceinline__ ull pack2(float lo, float hi) {
    ull r;
    asm("mov.b64 %0, {%1, %2};" : "=l"(r) : "f"(lo), "f"(hi));
    return r;
}
__device__ __forceinline__ float hadd2(ull v) {
    float lo, hi;
    asm("mov.b64 {%0, %1}, %2;" : "=f"(lo), "=f"(hi) : "l"(v));
    return lo + hi;
}

// ---- tf32 helpers ----
__device__ __forceinline__ unsigned cvt_tf32(float v) {
    unsigned r;
    asm("cvt.rna.tf32.f32 %0, %1;" : "=r"(r) : "f"(v));
    return r;
}
__device__ __forceinline__ void mma_tf32(float& d0, float& d1, float& d2, float& d3,
                                         unsigned a0, unsigned a1, unsigned a2, unsigned a3,
                                         unsigned b0, unsigned b1) {
    asm("mma.sync.aligned.m16n8k8.row.col.f32.tf32.tf32.f32 "
        "{%0,%1,%2,%3}, {%4,%5,%6,%7}, {%8,%9}, {%0,%1,%2,%3};"
        : "+f"(d0), "+f"(d1), "+f"(d2), "+f"(d3)
        : "r"(a0), "r"(a1), "r"(a2), "r"(a3), "r"(b0), "r"(b1));
}

// ---- MUFU-free expf. Magic-number rint + deg-5 poly for 2^f. ----
__device__ __forceinline__ float fast_exp(float x) {
    const float L2E   = 1.4426950408889634f;
    const float MAGIC = 12582912.0f;          // 1.5 * 2^23
    x = fmaxf(x, -80.0f);
    float y = fmaf(x, L2E, MAGIC);
    float f = fmaf(x, L2E, MAGIC - y);
    float p = 1.3333558146428443e-3f;
    p = fmaf(p, f, 9.6181291076284771e-3f);
    p = fmaf(p, f, 5.5504108664821579e-2f);
    p = fmaf(p, f, 2.4022650695910071e-1f);
    p = fmaf(p, f, 6.9314718055994531e-1f);
    p = fmaf(p, f, 1.0f);
    return __int_as_float(__float_as_int(p) + (__float_as_int(y) << 23));
}

#define BAR_G() asm volatile("bar.sync %0, %1;" :: "r"(g + 1), "r"(128) : "memory")

// Folded weights (computed by the prologue each call — deterministic).
// g_Wvc is pre-rounded to tf32 (it is ONLY consumed by the tf32 MMA).
__device__ float g_Wvc[CC * DD];
__device__ float g_M[CC * CC];

// ---------------------------------------------------------------------------
// Prologue (512 threads, 2 blocks):
//   block 0: g_Wvc fold (tf32-rounded), h-split + smem reduce
//   block 1: g_M — q-fold / k-fold in parallel halves, then split-d dot
// ---------------------------------------------------------------------------
__global__ void __launch_bounds__(512)
prologue_kernel(const float* __restrict__ Wk, const float* __restrict__ Wq,
                const float* __restrict__ Wv, const float* __restrict__ Wdk,
                const float* __restrict__ Wdq, const float* __restrict__ Wdv) {
    __shared__ float buf[10752];

    int tid  = threadIdx.x;
    int d    = tid & 255;
    int half = tid >> 8;

    if (blockIdx.x == 0) {
        float* w1s  = buf;
        float* part = buf + 1024;
        for (int i = tid; i < CC * HH; i += 512) w1s[i] = Wv[i];
        __syncthreads();

        float w2r[32];
#pragma unroll
        for (int hh = 0; hh < 32; hh++) w2r[hh] = Wdv[(half * 32 + hh) * DD + d];

        float acc[CC];
#pragma unroll
        for (int c = 0; c < CC; c++) {
            float a0 = 0.f, a1 = 0.f;
#pragma unroll
            for (int hh = 0; hh < 32; hh += 2) {
                a0 += w1s[c * HH + half * 32 + hh]     * w2r[hh];
                a1 += w1s[c * HH + half * 32 + hh + 1] * w2r[hh + 1];
            }
            acc[c] = a0 + a1;
        }
        if (half == 1)
#pragma unroll
            for (int c = 0; c < CC; c++) part[c * DD + d] = acc[c];
        __syncthreads();
        if (half == 0)
#pragma unroll
            for (int c = 0; c < CC; c++)
                g_Wvc[c * DD + d] = __uint_as_float(cvt_tf32(acc[c] + part[c * DD + d]));
    } else {
        float* w1a  = buf;
        float* w1b  = buf + 1024;
        float* qcs  = buf + 2048;
        float* kcs  = buf + 2048 + 4096;
        float* dotp = buf + 2048 + 8192;

        for (int i = tid; i < CC * HH; i += 512) { w1a[i] = Wq[i]; w1b[i] = Wk[i]; }
        __syncthreads();

        const float* W2 = half ? Wdk : Wdq;
        const float* w1 = half ? w1b : w1a;
        float* ocs = half ? kcs : qcs;
        float w2r[HH];
#pragma unroll
        for (int h = 0; h < HH; h++) w2r[h] = W2[h * DD + d];
#pragma unroll
        for (int c = 0; c < CC; c++) {
            float a0 = 0.f, a1 = 0.f;
#pragma unroll
            for (int h = 0; h < HH; h += 2) {
                a0 += w1[c * HH + h]     * w2r[h];
                a1 += w1[c * HH + h + 1] * w2r[h + 1];
            }
            ocs[d * CC + c] = a0 + a1;
        }
        __syncthreads();

        int c  = (tid & 255) >> 4;
        int c2 = tid & 15;
        int d0 = half * 128;
        float s0 = 0.f, s1 = 0.f;
#pragma unroll 8
        for (int dd = d0; dd < d0 + 128; dd += 2) {
            s0 += qcs[dd * CC + c] * kcs[dd * CC + c2];
            s1 += qcs[(dd + 1) * CC + c] * kcs[(dd + 1) * CC + c2];
        }
        dotp[tid] = s0 + s1;
        __syncthreads();
        if (half == 0)
            g_M[c * CC + c2] = (dotp[tid] + dotp[tid + 256]) * 0.25f;
    }
}

// ---------------------------------------------------------------------------
// Main kernel: two independent 128-thread groups per CTA (named barriers).
// Fused y+logits+softmax+z unchanged from R11 (bit-identical fp32).
// OUT PROJECTION ON TENSOR CORES: mma.sync.m16n8k8.tf32 register fragments.
//   A = z (smem, stride RS=20 -> conflict-free fragment loads, rows >=100 = 0)
//   B = Wvc (smem copy, stride 264 -> conflict-free), pre-rounded tf32
//   7 m-tiles x 8 n-tiles per warp x 2 k-steps, fp32 accumulators.
// ---------------------------------------------------------------------------
__global__ void __launch_bounds__(256, 3)
head_kernel(const float* __restrict__ x, float* __restrict__ out, int B) {
    extern __shared__ float sm[];
    const int tid  = threadIdx.x;
    const int g    = tid >> 7;       // group 0/1
    const int gtid = tid & 127;
    const int wg   = (tid >> 5) & 3; // warp in group
    const int lane = tid & 31;

    float* xs  = sm + g * (2 * TT * RS);   // 2000
    float* yz  = xs + TT * RS;             // 2000 (z)
    float* Ms  = sm + 4 * TT * RS;         // 256
    float* wvs = Ms + CC * CC;             // CC*WVS = 4224 (shared by both groups)

    const long long b = 2LL * blockIdx.x + g;
    const float* xb = x + b * (long long)(TT * CC);

    // x tile via float4 loads + M + Wvc->smem (whole CTA cooperates on wvs)
    for (int i = gtid; i < (TT * CC) / 4; i += 128) {
        float4 v = reinterpret_cast<const float4*>(xb)[i];
        int t = i >> 2, c4 = (i & 3) * 4;
        *reinterpret_cast<float4*>(&xs[t * RS + c4]) = v;
    }
    Ms[tid] = g_M[tid];   // CC*CC == 256 == blockDim
    for (int i = tid; i < CC * DD; i += 256)
        wvs[(i >> 8) * WVS + (i & 255)] = g_Wvc[i];
    __syncthreads();

    // ---- fused y + logits + softmax + z: one barrier-free stretch ----
    {
        const int blk = g ? (3 - wg) : wg;     // SMSP anti-correlation
        const bool rowAct = (lane < 25);
        const int t  = 25 * blk + lane;
        const int tl = rowAct ? t : 25 * blk;
        const int sEnd = (25 * blk + 26) & ~1; // 26 / 50 / 76 / 100

        float xf[16];
#pragma unroll
        for (int q = 0; q < 4; q++) {
            float4 v = *reinterpret_cast<const float4*>(&xs[tl * RS + 4 * q]);
            xf[4 * q] = v.x; xf[4 * q + 1] = v.y;
            xf[4 * q + 2] = v.z; xf[4 * q + 3] = v.w;
        }

        ull yr[8];
#pragma unroll
        for (int j = 0; j < 8; j++) yr[j] = 0ull;
#pragma unroll
        for (int c = 0; c < CC; c++) {
            ull xp = pack2(xf[c], xf[c]);
            ulonglong2 m0 = *reinterpret_cast<const ulonglong2*>(&Ms[c * CC + 0]);
            ulonglong2 m1 = *reinterpret_cast<const ulonglong2*>(&Ms[c * CC + 4]);
            ulonglong2 m2 = *reinterpret_cast<const ulonglong2*>(&Ms[c * CC + 8]);
            ulonglong2 m3 = *reinterpret_cast<const ulonglong2*>(&Ms[c * CC + 12]);
            yr[0] = ffma2(xp, m0.x, yr[0]);  yr[1] = ffma2(xp, m0.y, yr[1]);
            yr[2] = ffma2(xp, m1.x, yr[2]);  yr[3] = ffma2(xp, m1.y, yr[3]);
            yr[4] = ffma2(xp, m2.x, yr[4]);  yr[5] = ffma2(xp, m2.y, yr[5]);
            yr[6] = ffma2(xp, m3.x, yr[6]);  yr[7] = ffma2(xp, m3.y, yr[7]);
        }

        ull z[8];
#pragma unroll
        for (int j = 0; j < 8; j++) z[j] = 0ull;
        float sum = 0.f;

        const float* xp2 = xs;
        for (int s = 0; s < sEnd; s += 2, xp2 += 2 * RS) {
            ulonglong2 xa0 = *reinterpret_cast<const ulonglong2*>(xp2 + 0);
            ulonglong2 xb0 = *reinterpret_cast<const ulonglong2*>(xp2 + 4);
            ulonglong2 xc0 = *reinterpret_cast<const ulonglong2*>(xp2 + 8);
            ulonglong2 xd0 = *reinterpret_cast<const ulonglong2*>(xp2 + 12);
            ulonglong2 xa1 = *reinterpret_cast<const ulonglong2*>(xp2 + RS + 0);
            ulonglong2 xb1 = *reinterpret_cast<const ulonglong2*>(xp2 + RS + 4);
            ulonglong2 xc1 = *reinterpret_cast<const ulonglong2*>(xp2 + RS + 8);
            ulonglong2 xd1 = *reinterpret_cast<const ulonglong2*>(xp2 + RS + 12);

            ull A0 = 0ull, B0 = 0ull, A1 = 0ull, B1 = 0ull;
            A0 = ffma2(yr[0], xa0.x, A0);  B0 = ffma2(yr[1], xa0.y, B0);
            A1 = ffma2(yr[0], xa1.x, A1);  B1 = ffma2(yr[1], xa1.y, B1);
            A0 = ffma2(yr[2], xb0.x, A0);  B0 = ffma2(yr[3], xb0.y, B0);
            A1 = ffma2(yr[2], xb1.x, A1);  B1 = ffma2(yr[3], xb1.y, B1);
            A0 = ffma2(yr[4], xc0.x, A0);  B0 = ffma2(yr[5], xc0.y, B0);
            A1 = ffma2(yr[4], xc1.x, A1);  B1 = ffma2(yr[5], xc1.y, B1);
            A0 = ffma2(yr[6], xd0.x, A0);  B0 = ffma2(yr[7], xd0.y, B0);
            A1 = ffma2(yr[6], xd1.x, A1);  B1 = ffma2(yr[7], xd1.y, B1);

            float e0 = fast_exp(hadd2(add2(A0, B0)));
            float e1 = fast_exp(hadd2(add2(A1, B1)));
            e0 = (rowAct && s     <= t) ? e0 : 0.f;
            e1 = (rowAct && s + 1 <= t) ? e1 : 0.f;
            sum += e0 + e1;
            ull ep0 = pack2(e0, e0);
            ull ep1 = pack2(e1, e1);
            z[0] = ffma2(ep0, xa0.x, z[0]);  z[0] = ffma2(ep1, xa1.x, z[0]);
            z[1] = ffma2(ep0, xa0.y, z[1]);  z[1] = ffma2(ep1, xa1.y, z[1]);
            z[2] = ffma2(ep0, xb0.x, z[2]);  z[2] = ffma2(ep1, xb1.x, z[2]);
            z[3] = ffma2(ep0, xb0.y, z[3]);  z[3] = ffma2(ep1, xb1.y, z[3]);
            z[4] = ffma2(ep0, xc0.x, z[4]);  z[4] = ffma2(ep1, xc1.x, z[4]);
            z[5] = ffma2(ep0, xc0.y, z[5]);  z[5] = ffma2(ep1, xc1.y, z[5]);
            z[6] = ffma2(ep0, xd0.x, z[6]);  z[6] = ffma2(ep1, xd1.x, z[6]);
            z[7] = ffma2(ep0, xd0.y, z[7]);  z[7] = ffma2(ep1, xd1.y, z[7]);
        }

        if (rowAct) {
            float inv = 1.f / sum;
            ull ip = pack2(inv, inv);
#pragma unroll
            for (int j = 0; j < 8; j++)
                *reinterpret_cast<ull*>(&yz[t * RS + 2 * j]) = mul2(z[j], ip);
        }
    }
    BAR_G();

    // ---- out = z @ Wvc on tensor cores (m16n8k8 tf32) ----
    {
        const int g4  = lane >> 2;   // 0..7
        const int tig = lane & 3;    // 0..3
        float* ob = out + b * (long long)(TT * DD);

        for (int mt = 0; mt < 7; mt++) {
            int r0 = mt * 16 + g4;   // rows for a0/a2 (and d0/d1)
            int r1 = r0 + 8;         // rows for a1/a3 (and d2/d3)

            unsigned a[2][4];
#pragma unroll
            for (int ks = 0; ks < 2; ks++) {
                float v0 = (r0 < TT) ? yz[r0 * RS + ks * 8 + tig]     : 0.f;
                float v1 = (r1 < TT) ? yz[r1 * RS + ks * 8 + tig]     : 0.f;
                float v2 = (r0 < TT) ? yz[r0 * RS + ks * 8 + tig + 4] : 0.f;
                float v3 = (r1 < TT) ? yz[r1 * RS + ks * 8 + tig + 4] : 0.f;
                a[ks][0] = cvt_tf32(v0);
                a[ks][1] = cvt_tf32(v1);
                a[ks][2] = cvt_tf32(v2);
                a[ks][3] = cvt_tf32(v3);
            }

#pragma unroll
            for (int ni = 0; ni < 8; ni++) {
                int n0 = (wg * 8 + ni) * 8;   // base output column of this tile
                float d0 = 0.f, d1 = 0.f, d2 = 0.f, d3 = 0.f;
#pragma unroll
                for (int ks = 0; ks < 2; ks++) {
                    unsigned b0 = __float_as_uint(wvs[(ks * 8 + tig)     * WVS + n0 + g4]);
                    unsigned b1 = __float_as_uint(wvs[(ks * 8 + tig + 4) * WVS + n0 + g4]);
                    mma_tf32(d0, d1, d2, d3,
                             a[ks][0], a[ks][1], a[ks][2], a[ks][3], b0, b1);
                }
                if (r0 < TT) {
                    float2 o = make_float2(d0, d1);
                    *reinterpret_cast<float2*>(&ob[r0 * DD + n0 + tig * 2]) = o;
                }
                if (r1 < TT) {
                    float2 o = make_float2(d2, d3);
                    *reinterpret_cast<float2*>(&ob[r1 * DD + n0 + tig * 2]) = o;
                }
            }
        }
    }
}

// ---------------------------------------------------------------------------
extern "C" void kernel_launch(void* const* d_in, const int* in_sizes, int n_in,
                              void* d_out, int out_size) {
    const float* x   = (const float*)d_in[0];
    const float* Wk  = (const float*)d_in[1];
    const float* Wq  = (const float*)d_in[2];
    const float* Wv  = (const float*)d_in[3];
    const float* Wdk = (const float*)d_in[4];
    const float* Wdq = (const float*)d_in[5];
    const float* Wdv = (const float*)d_in[6];
    float* out = (float*)d_out;

    int B = in_sizes[0] / (TT * CC);  // 4096

    const int smem_bytes = (4 * TT * RS + CC * CC + CC * WVS) * (int)sizeof(float); // 49920
    cudaFuncSetAttribute(head_kernel, cudaFuncAttributeMaxDynamicSharedMemorySize, smem_bytes);

    prologue_kernel<<<2, 512>>>(Wk, Wq, Wv, Wdk, Wdq, Wdv);
    head_kernel<<<B / 2, 256, smem_bytes>>>(x, out, B);
}

// round 14
// speedup vs baseline: 1.0092x; 1.0009x over previous
#include <cuda_runtime.h>

#define TT 100   // sequence length
#define CC 16    // input embedding dim
#define HH 64    // head size
#define DD 256   // dense dim
#define RS 20    // padded row stride (also conflict-free for mma A-fragments)
#define WVS 264  // Wvc smem row stride (conflict-free B-fragments)

typedef unsigned long long ull;

// ---- packed fp32x2 helpers (sm_100+; .rn = bit-identical rounding to FFMA) ----
__device__ __forceinline__ ull ffma2(ull a, ull b, ull acc) {
    ull d;
    asm("fma.rn.f32x2 %0, %1, %2, %3;" : "=l"(d) : "l"(a), "l"(b), "l"(acc));
    return d;
}
__device__ __forceinline__ ull add2(ull a, ull b) {
    ull d;
    asm("add.rn.f32x2 %0, %1, %2;" : "=l"(d) : "l"(a), "l"(b));
    return d;
}
__device__ __forceinline__ ull mul2(ull a, ull b) {
    ull d;
    asm("mul.rn.f32x2 %0, %1, %2;" : "=l"(d) : "l"(a), "l"(b));
    return d;
}
__device__ __forceinline__ ull pack2(float lo, float hi) {
    ull r;
    asm("mov.b64 %0, {%1, %2};" : "=l"(r) : "f"(lo), "f"(hi));
    return r;
}
__device__ __forceinline__ float hadd2(ull v) {
    float lo, hi;
    asm("mov.b64 {%0, %1}, %2;" : "=f"(lo), "=f"(hi) : "l"(v));
    return lo + hi;
}

// ---- tf32 helpers ----
__device__ __forceinline__ unsigned cvt_tf32(float v) {
    unsigned r;
    asm("cvt.rna.tf32.f32 %0, %1;" : "=r"(r) : "f"(v));
    return r;
}
__device__ __forceinline__ void mma_tf32(float& d0, float& d1, float& d2, float& d3,
                                         unsigned a0, unsigned a1, unsigned a2, unsigned a3,
                                         unsigned b0, unsigned b1) {
    asm("mma.sync.aligned.m16n8k8.row.col.f32.tf32.tf32.f32 "
        "{%0,%1,%2,%3}, {%4,%5,%6,%7}, {%8,%9}, {%0,%1,%2,%3};"
        : "+f"(d0), "+f"(d1), "+f"(d2), "+f"(d3)
        : "r"(a0), "r"(a1), "r"(a2), "r"(a3), "r"(b0), "r"(b1));
}

// ---- MUFU-free expf. Magic-number rint + deg-5 poly for 2^f. ----
__device__ __forceinline__ float fast_exp(float x) {
    const float L2E   = 1.4426950408889634f;
    const float MAGIC = 12582912.0f;          // 1.5 * 2^23
    x = fmaxf(x, -80.0f);
    float y = fmaf(x, L2E, MAGIC);
    float f = fmaf(x, L2E, MAGIC - y);
    float p = 1.3333558146428443e-3f;
    p = fmaf(p, f, 9.6181291076284771e-3f);
    p = fmaf(p, f, 5.5504108664821579e-2f);
    p = fmaf(p, f, 2.4022650695910071e-1f);
    p = fmaf(p, f, 6.9314718055994531e-1f);
    p = fmaf(p, f, 1.0f);
    return __int_as_float(__float_as_int(p) + (__float_as_int(y) << 23));
}

#define BAR_G() asm volatile("bar.sync %0, %1;" :: "r"(g + 1), "r"(128) : "memory")

// Folded weights (computed by the prologue each call — deterministic).
// g_Wvc is pre-rounded to tf32 (it is ONLY consumed by the tf32 MMA).
__device__ float g_Wvc[CC * DD];
__device__ float g_M[CC * CC];

// ---------------------------------------------------------------------------
// Prologue (512 threads, 2 blocks):
//   block 0: g_Wvc fold (tf32-rounded), h-split + smem reduce
//   block 1: g_M — q-fold / k-fold in parallel halves, then split-d dot
// ---------------------------------------------------------------------------
__global__ void __launch_bounds__(512)
prologue_kernel(const float* __restrict__ Wk, const float* __restrict__ Wq,
                const float* __restrict__ Wv, const float* __restrict__ Wdk,
                const float* __restrict__ Wdq, const float* __restrict__ Wdv) {
    __shared__ float buf[10752];

    int tid  = threadIdx.x;
    int d    = tid & 255;
    int half = tid >> 8;

    if (blockIdx.x == 0) {
        float* w1s  = buf;
        float* part = buf + 1024;
        for (int i = tid; i < CC * HH; i += 512) w1s[i] = Wv[i];
        __syncthreads();

        float w2r[32];
#pragma unroll
        for (int hh = 0; hh < 32; hh++) w2r[hh] = Wdv[(half * 32 + hh) * DD + d];

        float acc[CC];
#pragma unroll
        for (int c = 0; c < CC; c++) {
            float a0 = 0.f, a1 = 0.f;
#pragma unroll
            for (int hh = 0; hh < 32; hh += 2) {
                a0 += w1s[c * HH + half * 32 + hh]     * w2r[hh];
                a1 += w1s[c * HH + half * 32 + hh + 1] * w2r[hh + 1];
            }
            acc[c] = a0 + a1;
        }
        if (half == 1)
#pragma unroll
            for (int c = 0; c < CC; c++) part[c * DD + d] = acc[c];
        __syncthreads();
        if (half == 0)
#pragma unroll
            for (int c = 0; c < CC; c++)
                g_Wvc[c * DD + d] = __uint_as_float(cvt_tf32(acc[c] + part[c * DD + d]));
    } else {
        float* w1a  = buf;
        float* w1b  = buf + 1024;
        float* qcs  = buf + 2048;
        float* kcs  = buf + 2048 + 4096;
        float* dotp = buf + 2048 + 8192;

        for (int i = tid; i < CC * HH; i += 512) { w1a[i] = Wq[i]; w1b[i] = Wk[i]; }
        __syncthreads();

        const float* W2 = half ? Wdk : Wdq;
        const float* w1 = half ? w1b : w1a;
        float* ocs = half ? kcs : qcs;
        float w2r[HH];
#pragma unroll
        for (int h = 0; h < HH; h++) w2r[h] = W2[h * DD + d];
#pragma unroll
        for (int c = 0; c < CC; c++) {
            float a0 = 0.f, a1 = 0.f;
#pragma unroll
            for (int h = 0; h < HH; h += 2) {
                a0 += w1[c * HH + h]     * w2r[h];
                a1 += w1[c * HH + h + 1] * w2r[h + 1];
            }
            ocs[d * CC + c] = a0 + a1;
        }
        __syncthreads();

        int c  = (tid & 255) >> 4;
        int c2 = tid & 15;
        int d0 = half * 128;
        float s0 = 0.f, s1 = 0.f;
#pragma unroll 8
        for (int dd = d0; dd < d0 + 128; dd += 2) {
            s0 += qcs[dd * CC + c] * kcs[dd * CC + c2];
            s1 += qcs[(dd + 1) * CC + c] * kcs[(dd + 1) * CC + c2];
        }
        dotp[tid] = s0 + s1;
        __syncthreads();
        if (half == 0)
            g_M[c * CC + c2] = (dotp[tid] + dotp[tid + 256]) * 0.25f;
    }
}

// ---------------------------------------------------------------------------
// Main kernel: two independent 128-thread groups per CTA (named barriers).
// Fused y+logits+softmax+z unchanged from R11 (bit-identical fp32).
// OUT PROJECTION ON TENSOR CORES: mma.sync.m16n8k8.tf32 register fragments.
//   A = z (smem, stride RS=20 -> conflict-free fragment loads, rows >=100 = 0)
//   B = Wvc (smem copy, stride 264 -> conflict-free), pre-rounded tf32
//   7 m-tiles x 8 n-tiles per warp x 2 k-steps, fp32 accumulators.
// ---------------------------------------------------------------------------
__global__ void __launch_bounds__(256, 3)
head_kernel(const float* __restrict__ x, float* __restrict__ out, int B) {
    extern __shared__ float sm[];
    const int tid  = threadIdx.x;
    const int g    = tid >> 7;       // group 0/1
    const int gtid = tid & 127;
    const int wg   = (tid >> 5) & 3; // warp in group
    const int lane = tid & 31;

    float* xs  = sm + g * (2 * TT * RS);   // 2000
    float* yz  = xs + TT * RS;             // 2000 (z)
    float* Ms  = sm + 4 * TT * RS;         // 256
    float* wvs = Ms + CC * CC;             // CC*WVS = 4224 (shared by both groups)

    const long long b = 2LL * blockIdx.x + g;
    const float* xb = x + b * (long long)(TT * CC);

    // x tile via float4 loads + M + Wvc->smem (whole CTA cooperates on wvs)
    for (int i = gtid; i < (TT * CC) / 4; i += 128) {
        float4 v = reinterpret_cast<const float4*>(xb)[i];
        int t = i >> 2, c4 = (i & 3) * 4;
        *reinterpret_cast<float4*>(&xs[t * RS + c4]) = v;
    }
    Ms[tid] = g_M[tid];   // CC*CC == 256 == blockDim
    for (int i = tid; i < CC * DD; i += 256)
        wvs[(i >> 8) * WVS + (i & 255)] = g_Wvc[i];
    __syncthreads();

    // ---- fused y + logits + softmax + z: one barrier-free stretch ----
    {
        const int blk = g ? (3 - wg) : wg;     // SMSP anti-correlation
        const bool rowAct = (lane < 25);
        const int t  = 25 * blk + lane;
        const int tl = rowAct ? t : 25 * blk;
        const int sEnd = (25 * blk + 26) & ~1; // 26 / 50 / 76 / 100

        float xf[16];
#pragma unroll
        for (int q = 0; q < 4; q++) {
            float4 v = *reinterpret_cast<const float4*>(&xs[tl * RS + 4 * q]);
            xf[4 * q] = v.x; xf[4 * q + 1] = v.y;
            xf[4 * q + 2] = v.z; xf[4 * q + 3] = v.w;
        }

        ull yr[8];
#pragma unroll
        for (int j = 0; j < 8; j++) yr[j] = 0ull;
#pragma unroll
        for (int c = 0; c < CC; c++) {
            ull xp = pack2(xf[c], xf[c]);
            ulonglong2 m0 = *reinterpret_cast<const ulonglong2*>(&Ms[c * CC + 0]);
            ulonglong2 m1 = *reinterpret_cast<const ulonglong2*>(&Ms[c * CC + 4]);
            ulonglong2 m2 = *reinterpret_cast<const ulonglong2*>(&Ms[c * CC + 8]);
            ulonglong2 m3 = *reinterpret_cast<const ulonglong2*>(&Ms[c * CC + 12]);
            yr[0] = ffma2(xp, m0.x, yr[0]);  yr[1] = ffma2(xp, m0.y, yr[1]);
            yr[2] = ffma2(xp, m1.x, yr[2]);  yr[3] = ffma2(xp, m1.y, yr[3]);
            yr[4] = ffma2(xp, m2.x, yr[4]);  yr[5] = ffma2(xp, m2.y, yr[5]);
            yr[6] = ffma2(xp, m3.x, yr[6]);  yr[7] = ffma2(xp, m3.y, yr[7]);
        }

        ull z[8];
#pragma unroll
        for (int j = 0; j < 8; j++) z[j] = 0ull;
        float sum = 0.f;

        const float* xp2 = xs;
        for (int s = 0; s < sEnd; s += 2, xp2 += 2 * RS) {
            ulonglong2 xa0 = *reinterpret_cast<const ulonglong2*>(xp2 + 0);
            ulonglong2 xb0 = *reinterpret_cast<const ulonglong2*>(xp2 + 4);
            ulonglong2 xc0 = *reinterpret_cast<const ulonglong2*>(xp2 + 8);
            ulonglong2 xd0 = *reinterpret_cast<const ulonglong2*>(xp2 + 12);
            ulonglong2 xa1 = *reinterpret_cast<const ulonglong2*>(xp2 + RS + 0);
            ulonglong2 xb1 = *reinterpret_cast<const ulonglong2*>(xp2 + RS + 4);
            ulonglong2 xc1 = *reinterpret_cast<const ulonglong2*>(xp2 + RS + 8);
            ulonglong2 xd1 = *reinterpret_cast<const ulonglong2*>(xp2 + RS + 12);

            ull A0 = 0ull, B0 = 0ull, A1 = 0ull, B1 = 0ull;
            A0 = ffma2(yr[0], xa0.x, A0);  B0 = ffma2(yr[1], xa0.y, B0);
            A1 = ffma2(yr[0], xa1.x, A1);  B1 = ffma2(yr[1], xa1.y, B1);
            A0 = ffma2(yr[2], xb0.x, A0);  B0 = ffma2(yr[3], xb0.y, B0);
            A1 = ffma2(yr[2], xb1.x, A1);  B1 = ffma2(yr[3], xb1.y, B1);
            A0 = ffma2(yr[4], xc0.x, A0);  B0 = ffma2(yr[5], xc0.y, B0);
            A1 = ffma2(yr[4], xc1.x, A1);  B1 = ffma2(yr[5], xc1.y, B1);
            A0 = ffma2(yr[6], xd0.x, A0);  B0 = ffma2(yr[7], xd0.y, B0);
            A1 = ffma2(yr[6], xd1.x, A1);  B1 = ffma2(yr[7], xd1.y, B1);

            float e0 = fast_exp(hadd2(add2(A0, B0)));
            float e1 = fast_exp(hadd2(add2(A1, B1)));
            e0 = (rowAct && s     <= t) ? e0 : 0.f;
            e1 = (rowAct && s + 1 <= t) ? e1 : 0.f;
            sum += e0 + e1;
            ull ep0 = pack2(e0, e0);
            ull ep1 = pack2(e1, e1);
            z[0] = ffma2(ep0, xa0.x, z[0]);  z[0] = ffma2(ep1, xa1.x, z[0]);
            z[1] = ffma2(ep0, xa0.y, z[1]);  z[1] = ffma2(ep1, xa1.y, z[1]);
            z[2] = ffma2(ep0, xb0.x, z[2]);  z[2] = ffma2(ep1, xb1.x, z[2]);
            z[3] = ffma2(ep0, xb0.y, z[3]);  z[3] = ffma2(ep1, xb1.y, z[3]);
            z[4] = ffma2(ep0, xc0.x, z[4]);  z[4] = ffma2(ep1, xc1.x, z[4]);
            z[5] = ffma2(ep0, xc0.y, z[5]);  z[5] = ffma2(ep1, xc1.y, z[5]);
            z[6] = ffma2(ep0, xd0.x, z[6]);  z[6] = ffma2(ep1, xd1.x, z[6]);
            z[7] = ffma2(ep0, xd0.y, z[7]);  z[7] = ffma2(ep1, xd1.y, z[7]);
        }

        if (rowAct) {
            float inv = 1.f / sum;
            ull ip = pack2(inv, inv);
#pragma unroll
            for (int j = 0; j < 8; j++)
                *reinterpret_cast<ull*>(&yz[t * RS + 2 * j]) = mul2(z[j], ip);
        }
    }
    BAR_G();

    // ---- out = z @ Wvc on tensor cores (m16n8k8 tf32) ----
    {
        const int g4  = lane >> 2;   // 0..7
        const int tig = lane & 3;    // 0..3
        float* ob = out + b * (long long)(TT * DD);

        for (int mt = 0; mt < 7; mt++) {
            int r0 = mt * 16 + g4;   // rows for a0/a2 (and d0/d1)
            int r1 = r0 + 8;         // rows for a1/a3 (and d2/d3)

            unsigned a[2][4];
#pragma unroll
            for (int ks = 0; ks < 2; ks++) {
                float v0 = (r0 < TT) ? yz[r0 * RS + ks * 8 + tig]     : 0.f;
                float v1 = (r1 < TT) ? yz[r1 * RS + ks * 8 + tig]     : 0.f;
                float v2 = (r0 < TT) ? yz[r0 * RS + ks * 8 + tig + 4] : 0.f;
                float v3 = (r1 < TT) ? yz[r1 * RS + ks * 8 + tig + 4] : 0.f;
                a[ks][0] = cvt_tf32(v0);
                a[ks][1] = cvt_tf32(v1);
                a[ks][2] = cvt_tf32(v2);
                a[ks][3] = cvt_tf32(v3);
            }

#pragma unroll
            for (int ni = 0; ni < 8; ni++) {
                int n0 = (wg * 8 + ni) * 8;   // base output column of this tile
                float d0 = 0.f, d1 = 0.f, d2 = 0.f, d3 = 0.f;
#pragma unroll
                for (int ks = 0; ks < 2; ks++) {
                    unsigned b0 = __float_as_uint(wvs[(ks * 8 + tig)     * WVS + n0 + g4]);
                    unsigned b1 = __float_as_uint(wvs[(ks * 8 + tig + 4) * WVS + n0 + g4]);
                    mma_tf32(d0, d1, d2, d3,
                             a[ks][0], a[ks][1], a[ks][2], a[ks][3], b0, b1);
                }
                if (r0 < TT) {
                    float2 o = make_float2(d0, d1);
                    *reinterpret_cast<float2*>(&ob[r0 * DD + n0 + tig * 2]) = o;
                }
                if (r1 < TT) {
                    float2 o = make_float2(d2, d3);
                    *reinterpret_cast<float2*>(&ob[r1 * DD + n0 + tig * 2]) = o;
                }
            }
        }
    }
}

// ---------------------------------------------------------------------------
extern "C" void kernel_launch(void* const* d_in, const int* in_sizes, int n_in,
                              void* d_out, int out_size) {
    const float* x   = (const float*)d_in[0];
    const float* Wk  = (const float*)d_in[1];
    const float* Wq  = (const float*)d_in[2];
    const float* Wv  = (const float*)d_in[3];
    const float* Wdk = (const float*)d_in[4];
    const float* Wdq = (const float*)d_in[5];
    const float* Wdv = (const float*)d_in[6];
    float* out = (float*)d_out;

    int B = in_sizes[0] / (TT * CC);  // 4096

    const int smem_bytes = (4 * TT * RS + CC * CC + CC * WVS) * (int)sizeof(float); // 49920
    cudaFuncSetAttribute(head_kernel, cudaFuncAttributeMaxDynamicSharedMemorySize, smem_bytes);

    prologue_kernel<<<2, 512>>>(Wk, Wq, Wv, Wdk, Wdq, Wdv);
    head_kernel<<<B / 2, 256, smem_bytes>>>(x, out, B);
}